// round 4
// baseline (speedup 1.0000x reference)
#include <cuda_runtime.h>
#include <cuda_bf16.h>
#include <cstdint>

#define NMAX 100000
#define EMAX 1600000
#define DD   128

// ---------------- scratch: referenced ONLY from device code by symbol -------
__device__ float g_h  [(size_t)NMAX * DD];   // dis[i]*(W x + b), gather source
__device__ float g_agg[(size_t)NMAX * DD];   // aggregation accumulator
__device__ float g_dis[NMAX];                // deg^-0.5
__device__ int   g_row[EMAX];
__device__ int   g_col[EMAX];

// ---------------- prep ------------------------------------------------------
__global__ void k_deg_init(int n) {
    int i = blockIdx.x * blockDim.x + threadIdx.x;
    if (i < n) g_dis[i] = 1.0f;   // self loop contributes 1 to deg
}

// edge_index arrives as int32 (harness converts int64 -> int32)
__global__ void k_deg_count(const int* __restrict__ ei, int e, int n) {
    int i = blockIdx.x * blockDim.x + threadIdx.x;
    if (i < e) {
        int r = ei[i];
        int c = ei[e + i];
        if ((unsigned)r >= (unsigned)n) r = 0;
        if ((unsigned)c >= (unsigned)n) c = 0;
        g_row[i] = r;
        g_col[i] = c;
        atomicAdd(&g_dis[r], 1.0f);
    }
}

__global__ void k_deg_fin(int n) {
    int i = blockIdx.x * blockDim.x + threadIdx.x;
    if (i < n) g_dis[i] = rsqrtf(g_dis[i]);
}

// ---------------- GEMM: g_h = g_agg = dis[i] * (in @ W^T + b) ----------------
// in_ext == nullptr -> read g_h (layers 2,3; in-place safe: tile-local rows).
__global__ __launch_bounds__(256) void k_gemm(
    const float* __restrict__ in_ext, const float* __restrict__ W,
    const float* __restrict__ bias, int n)
{
    __shared__ float in_s[128 * 36];   // [row][kc] stride 36
    __shared__ float w_s [32 * 128];   // [kc][j]

    const float* in = in_ext ? in_ext : g_h;

    const int tid  = threadIdx.x;
    const int base = blockIdx.x * 128;
    const int tr   = tid >> 4;     // 0..15  -> rows tr*8 .. tr*8+7
    const int tc   = tid & 15;     // 0..15  -> cols jj*16 + tc

    float acc[8][8];
#pragma unroll
    for (int i = 0; i < 8; i++)
#pragma unroll
        for (int j = 0; j < 8; j++) acc[i][j] = 0.0f;

    for (int kt = 0; kt < 4; kt++) {
        for (int idx = tid; idx < 128 * 8; idx += 256) {
            int r = idx >> 3, kq = idx & 7;
            float4 v = make_float4(0.f, 0.f, 0.f, 0.f);
            int gr = base + r;
            if (gr < n) v = *(const float4*)(in + (size_t)gr * DD + kt * 32 + kq * 4);
            float* p = in_s + r * 36 + kq * 4;
            p[0] = v.x; p[1] = v.y; p[2] = v.z; p[3] = v.w;
        }
        for (int idx = tid; idx < 128 * 8; idx += 256) {
            int j = idx >> 3, kq = idx & 7;
            float4 v = *(const float4*)(W + (size_t)j * DD + kt * 32 + kq * 4);
            w_s[(kq * 4 + 0) * 128 + j] = v.x;
            w_s[(kq * 4 + 1) * 128 + j] = v.y;
            w_s[(kq * 4 + 2) * 128 + j] = v.z;
            w_s[(kq * 4 + 3) * 128 + j] = v.w;
        }
        __syncthreads();

        const float* a_base = in_s + tr * 8 * 36;
#pragma unroll 8
        for (int k = 0; k < 32; k++) {
            float a[8];
#pragma unroll
            for (int i = 0; i < 8; i++) a[i] = a_base[i * 36 + k];
#pragma unroll
            for (int jj = 0; jj < 8; jj++) {
                float bv = w_s[k * 128 + jj * 16 + tc];
#pragma unroll
                for (int i = 0; i < 8; i++) acc[i][jj] = fmaf(a[i], bv, acc[i][jj]);
            }
        }
        __syncthreads();
    }

#pragma unroll
    for (int i = 0; i < 8; i++) {
        int r = base + tr * 8 + i;
        if (r < n) {
            float dv = g_dis[r];
#pragma unroll
            for (int jj = 0; jj < 8; jj++) {
                int j = jj * 16 + tc;
                float v = dv * (acc[i][jj] + bias[j]);
                size_t o = (size_t)r * DD + j;
                g_h[o]   = v;
                g_agg[o] = v;   // self-loop term pre-seeded
            }
        }
    }
}

// ---------------- edge scatter: agg[c] += h[r], one warp per edge -----------
// Scalar atomicAdd with unused return -> REDG (no-return global reduction).
__global__ __launch_bounds__(256) void k_scatter(int e)
{
    int gt = blockIdx.x * blockDim.x + threadIdx.x;
    int w  = gt >> 5;
    int lane = gt & 31;
    if (w >= e) return;
    int r = g_row[w];
    int c = g_col[w];
    const float4* src = (const float4*)(g_h + (size_t)r * DD) + lane;
    float* dst = g_agg + (size_t)c * DD + lane * 4;
    float4 v = *src;
    atomicAdd(dst + 0, v.x);
    atomicAdd(dst + 1, v.y);
    atomicAdd(dst + 2, v.z);
    atomicAdd(dst + 3, v.w);
}

// ---------------- post: relu(dis[c] * agg) -> g_h (or d_out on last layer) ---
__global__ void k_post(float* __restrict__ out_ext, int n)
{
    int i = blockIdx.x * blockDim.x + threadIdx.x;   // float4 index
    int total = n * 32;
    if (i < total) {
        int r = i >> 5;
        float s = g_dis[r];
        float4 v = ((const float4*)g_agg)[i];
        v.x = fmaxf(v.x * s, 0.f);
        v.y = fmaxf(v.y * s, 0.f);
        v.z = fmaxf(v.z * s, 0.f);
        v.w = fmaxf(v.w * s, 0.f);
        if (out_ext) ((float4*)out_ext)[i] = v;
        else         ((float4*)g_h)[i]     = v;
    }
}

// ---------------- launcher ---------------------------------------------------
extern "C" void kernel_launch(void* const* d_in, const int* in_sizes, int n_in,
                              void* d_out, int out_size)
{
    // Identify inputs by element count (unambiguous for this problem):
    //   x: 12,800,000 f32 | edge_index: 3,200,000 i32 | W: 16,384 f32 x3 | b: 128 f32 x3
    const float* x = nullptr;
    const int* ei = nullptr;
    const float* Ws[3] = {nullptr, nullptr, nullptr};
    const float* bs[3] = {nullptr, nullptr, nullptr};
    int nx = 0, ne = 0, wi = 0, bi = 0;
    for (int i = 0; i < n_in; i++) {
        int sz = in_sizes[i];
        if (sz == DD * DD)       { if (wi < 3) Ws[wi++] = (const float*)d_in[i]; }
        else if (sz == DD)       { if (bi < 3) bs[bi++] = (const float*)d_in[i]; }
        else if (sz == 2 * EMAX) { ei = (const int*)d_in[i]; ne = sz; }
        else                     { x = (const float*)d_in[i]; nx = sz; }
    }
    if (!x || !ei || wi < 3 || bi < 3) {
        // positional fallback (reference order)
        x  = (const float*)d_in[0];  nx = in_sizes[0];
        ei = (const int*)d_in[1];    ne = in_sizes[1];
        Ws[0] = (const float*)d_in[2]; bs[0] = (const float*)d_in[3];
        Ws[1] = (const float*)d_in[4]; bs[1] = (const float*)d_in[5];
        Ws[2] = (const float*)d_in[6]; bs[2] = (const float*)d_in[7];
    }

    int n = nx / DD;  if (n > NMAX) n = NMAX;
    int e = ne / 2;   if (e > EMAX) e = EMAX;

    const int T = 256;
    k_deg_init <<<(n + T - 1) / T, T>>>(n);
    k_deg_count<<<(e + T - 1) / T, T>>>(ei, e, n);
    k_deg_fin  <<<(n + T - 1) / T, T>>>(n);

    const int gemm_blocks = (n + 127) / 128;
    const int scat_blocks = (int)(((long long)e * 32 + T - 1) / T);
    const int post_blocks = (n * 32 + T - 1) / T;

    // layer 1
    k_gemm   <<<gemm_blocks, 256>>>(x, Ws[0], bs[0], n);
    k_scatter<<<scat_blocks, T>>>(e);
    k_post   <<<post_blocks, T>>>(nullptr, n);
    // layer 2
    k_gemm   <<<gemm_blocks, 256>>>(nullptr, Ws[1], bs[1], n);
    k_scatter<<<scat_blocks, T>>>(e);
    k_post   <<<post_blocks, T>>>(nullptr, n);
    // layer 3
    k_gemm   <<<gemm_blocks, 256>>>(nullptr, Ws[2], bs[2], n);
    k_scatter<<<scat_blocks, T>>>(e);
    k_post   <<<post_blocks, T>>>((float*)d_out, n);
}

// round 5
// speedup vs baseline: 1.6107x; 1.6107x over previous
#include <cuda_runtime.h>
#include <cuda_bf16.h>
#include <cstdint>

#define NMAX 100000
#define EMAX 1600000
#define DD   128

// ---------------- scratch: referenced ONLY from device code by symbol -------
__device__ float g_h   [(size_t)NMAX * DD];  // dis[i]*(W x + b), gather source
__device__ float g_agg [(size_t)NMAX * DD];  // aggregation accumulator
__device__ float g_dis [NMAX];               // deg^-0.5
__device__ int2  g_edge[EMAX];               // (row, col) packed

// ---------------- prep ------------------------------------------------------
__global__ void k_deg_init(int n) {
    int i = blockIdx.x * blockDim.x + threadIdx.x;
    if (i < n) g_dis[i] = 1.0f;   // self loop contributes 1 to deg
}

// edge_index arrives as int32 (harness converts int64 -> int32)
__global__ void k_deg_count(const int* __restrict__ ei, int e, int n) {
    int i = blockIdx.x * blockDim.x + threadIdx.x;
    if (i < e) {
        int r = ei[i];
        int c = ei[e + i];
        if ((unsigned)r >= (unsigned)n) r = 0;
        if ((unsigned)c >= (unsigned)n) c = 0;
        g_edge[i] = make_int2(r, c);
        atomicAdd(&g_dis[r], 1.0f);
    }
}

__global__ void k_deg_fin(int n) {
    int i = blockIdx.x * blockDim.x + threadIdx.x;
    if (i < n) g_dis[i] = rsqrtf(g_dis[i]);
}

// ---------------- GEMM: g_h = g_agg = dis[i] * (in @ W^T + b) ----------------
// in_ext != null : plain load (layer 1, reads x)
// in_ext == null : load relu(dis[r] * g_agg[r])  (layers 2,3; fused post-pass)
// In-place safe: each block reads only its own 128 rows, all reads precede
// all writes within the block.
__global__ __launch_bounds__(256) void k_gemm(
    const float* __restrict__ in_ext, const float* __restrict__ W,
    const float* __restrict__ bias, int n)
{
    __shared__ float in_s[128 * 36];   // [row][k] k-contiguous, stride 36 (f4-aligned)
    __shared__ float w_s [128 * 36];   // [j][k]   k-contiguous, stride 36

    const int tid  = threadIdx.x;
    const int base = blockIdx.x * 128;
    const int tr   = tid >> 4;     // 0..15 -> rows tr*8 .. tr*8+7
    const int tc   = tid & 15;     // 0..15 -> cols jj*16 + tc

    float acc[8][8];
#pragma unroll
    for (int i = 0; i < 8; i++)
#pragma unroll
        for (int j = 0; j < 8; j++) acc[i][j] = 0.0f;

    for (int kt = 0; kt < 4; kt++) {
        // stage input rows (optionally fused relu(dis*agg))
        for (int idx = tid; idx < 128 * 8; idx += 256) {
            int r = idx >> 3, kq = idx & 7;
            int gr = base + r;
            float4 v = make_float4(0.f, 0.f, 0.f, 0.f);
            if (gr < n) {
                if (in_ext) {
                    v = *(const float4*)(in_ext + (size_t)gr * DD + kt * 32 + kq * 4);
                } else {
                    v = *(const float4*)(g_agg + (size_t)gr * DD + kt * 32 + kq * 4);
                    float s = g_dis[gr];
                    v.x = fmaxf(v.x * s, 0.f);
                    v.y = fmaxf(v.y * s, 0.f);
                    v.z = fmaxf(v.z * s, 0.f);
                    v.w = fmaxf(v.w * s, 0.f);
                }
            }
            *(float4*)(in_s + r * 36 + kq * 4) = v;
        }
        // stage W rows: w_s[j][k] = W[j][kt*32+k]  (no transpose)
        for (int idx = tid; idx < 128 * 8; idx += 256) {
            int j = idx >> 3, kq = idx & 7;
            float4 v = *(const float4*)(W + (size_t)j * DD + kt * 32 + kq * 4);
            *(float4*)(w_s + j * 36 + kq * 4) = v;
        }
        __syncthreads();

        const float* a_base = in_s + tr * 8 * 36;
        const float* b_base = w_s + tc * 36;
#pragma unroll
        for (int k4 = 0; k4 < 8; k4++) {
            float4 a4[8];
#pragma unroll
            for (int i = 0; i < 8; i++)
                a4[i] = *(const float4*)(a_base + i * 36 + k4 * 4);
#pragma unroll
            for (int jj = 0; jj < 8; jj++) {
                float4 b4 = *(const float4*)(b_base + jj * 16 * 36 + k4 * 4);
#pragma unroll
                for (int i = 0; i < 8; i++) {
                    acc[i][jj] = fmaf(a4[i].x, b4.x, acc[i][jj]);
                    acc[i][jj] = fmaf(a4[i].y, b4.y, acc[i][jj]);
                    acc[i][jj] = fmaf(a4[i].z, b4.z, acc[i][jj]);
                    acc[i][jj] = fmaf(a4[i].w, b4.w, acc[i][jj]);
                }
            }
        }
        __syncthreads();
    }

#pragma unroll
    for (int i = 0; i < 8; i++) {
        int r = base + tr * 8 + i;
        if (r < n) {
            float dv = g_dis[r];
#pragma unroll
            for (int jj = 0; jj < 8; jj++) {
                int j = jj * 16 + tc;
                float v = dv * (acc[i][jj] + bias[j]);
                size_t o = (size_t)r * DD + j;
                g_h[o]   = v;
                g_agg[o] = v;   // self-loop term pre-seeded
            }
        }
    }
}

// ---------------- edge scatter: agg[c] += h[r], one warp per edge -----------
// red.global.add.v4.f32: one 16B reduction per lane (4x fewer ops vs scalar).
__global__ __launch_bounds__(256) void k_scatter(int e)
{
    int gt = blockIdx.x * blockDim.x + threadIdx.x;
    int w  = gt >> 5;
    int lane = gt & 31;
    if (w >= e) return;
    int2 rc = g_edge[w];
    float4 v = *((const float4*)g_h + (size_t)rc.x * 32 + lane);
    float4* dst = (float4*)g_agg + (size_t)rc.y * 32 + lane;
    asm volatile("red.global.add.v4.f32 [%0], {%1,%2,%3,%4};"
                 :: "l"(dst), "f"(v.x), "f"(v.y), "f"(v.z), "f"(v.w)
                 : "memory");
}

// ---------------- final post: relu(dis[c] * agg) -> d_out --------------------
__global__ void k_post(float4* __restrict__ out, int n)
{
    int i = blockIdx.x * blockDim.x + threadIdx.x;   // float4 index
    int total = n * 32;
    if (i < total) {
        int r = i >> 5;
        float s = g_dis[r];
        float4 v = ((const float4*)g_agg)[i];
        v.x = fmaxf(v.x * s, 0.f);
        v.y = fmaxf(v.y * s, 0.f);
        v.z = fmaxf(v.z * s, 0.f);
        v.w = fmaxf(v.w * s, 0.f);
        out[i] = v;
    }
}

// ---------------- launcher ---------------------------------------------------
extern "C" void kernel_launch(void* const* d_in, const int* in_sizes, int n_in,
                              void* d_out, int out_size)
{
    // Identify inputs by element count (unambiguous for this problem):
    //   x: 12,800,000 f32 | edge_index: 3,200,000 i32 | W: 16,384 f32 x3 | b: 128 f32 x3
    const float* x = nullptr;
    const int* ei = nullptr;
    const float* Ws[3] = {nullptr, nullptr, nullptr};
    const float* bs[3] = {nullptr, nullptr, nullptr};
    int nx = 0, ne = 0, wi = 0, bi = 0;
    for (int i = 0; i < n_in; i++) {
        int sz = in_sizes[i];
        if (sz == DD * DD)       { if (wi < 3) Ws[wi++] = (const float*)d_in[i]; }
        else if (sz == DD)       { if (bi < 3) bs[bi++] = (const float*)d_in[i]; }
        else if (sz == 2 * EMAX) { ei = (const int*)d_in[i]; ne = sz; }
        else                     { x = (const float*)d_in[i]; nx = sz; }
    }
    if (!x || !ei || wi < 3 || bi < 3) {
        x  = (const float*)d_in[0];  nx = in_sizes[0];
        ei = (const int*)d_in[1];    ne = in_sizes[1];
        Ws[0] = (const float*)d_in[2]; bs[0] = (const float*)d_in[3];
        Ws[1] = (const float*)d_in[4]; bs[1] = (const float*)d_in[5];
        Ws[2] = (const float*)d_in[6]; bs[2] = (const float*)d_in[7];
    }

    int n = nx / DD;  if (n > NMAX) n = NMAX;
    int e = ne / 2;   if (e > EMAX) e = EMAX;

    const int T = 256;
    k_deg_init <<<(n + T - 1) / T, T>>>(n);
    k_deg_count<<<(e + T - 1) / T, T>>>(ei, e, n);
    k_deg_fin  <<<(n + T - 1) / T, T>>>(n);

    const int gemm_blocks = (n + 127) / 128;
    const int scat_blocks = (int)(((long long)e * 32 + T - 1) / T);
    const int post_blocks = (n * 32 + T - 1) / T;

    // layer 1
    k_gemm   <<<gemm_blocks, 256>>>(x, Ws[0], bs[0], n);
    k_scatter<<<scat_blocks, T>>>(e);
    // layer 2 (reads g_agg with fused relu(dis*.) in the load)
    k_gemm   <<<gemm_blocks, 256>>>(nullptr, Ws[1], bs[1], n);
    k_scatter<<<scat_blocks, T>>>(e);
    // layer 3
    k_gemm   <<<gemm_blocks, 256>>>(nullptr, Ws[2], bs[2], n);
    k_scatter<<<scat_blocks, T>>>(e);
    k_post   <<<post_blocks, T>>>((float4*)d_out, n);
}

// round 7
// speedup vs baseline: 2.9663x; 1.8417x over previous
#include <cuda_runtime.h>
#include <cuda_bf16.h>
#include <cstdint>

#define NMAX 100000
#define EMAX 1600000
#define DD   128

// ---------------- scratch ----------------------------------------------------
__device__ float g_h   [(size_t)NMAX * DD];  // gemm output: dis[i]*(W in + b)
__device__ float g_act [(size_t)NMAX * DD];  // agg output (next layer input)
__device__ float g_dis [NMAX];               // (1+outdeg)^-0.5
__device__ int2  g_edge[EMAX];               // (row=src, col=dst)
__device__ int   g_indeg [NMAX];
__device__ int   g_rowdeg[NMAX];
__device__ int   g_ptr   [NMAX + 1];         // CSR by destination
__device__ int   g_cursor[NMAX];
__device__ int   g_csr_src[EMAX];
__device__ int   g_bsum[256];
__device__ int   g_boff[256];

// ---------------- prep -------------------------------------------------------
__global__ void k_zero(int n) {
    int i = blockIdx.x * blockDim.x + threadIdx.x;
    if (i < n) { g_indeg[i] = 0; g_rowdeg[i] = 0; }
}

__global__ void k_count(const int* __restrict__ ei, int e, int n) {
    int i = blockIdx.x * blockDim.x + threadIdx.x;
    if (i < e) {
        int r = ei[i];
        int c = ei[e + i];
        if ((unsigned)r >= (unsigned)n) r = 0;
        if ((unsigned)c >= (unsigned)n) c = 0;
        g_edge[i] = make_int2(r, c);
        atomicAdd(&g_rowdeg[r], 1);
        atomicAdd(&g_indeg[c], 1);
    }
}

__global__ void k_scan_block(int n) {
    __shared__ int s[1024];
    int i = blockIdx.x * 1024 + threadIdx.x;
    int v = (i < n) ? g_indeg[i] : 0;
    s[threadIdx.x] = v;
    __syncthreads();
    for (int off = 1; off < 1024; off <<= 1) {
        int t = 0;
        if (threadIdx.x >= off) t = s[threadIdx.x - off];
        __syncthreads();
        if (threadIdx.x >= off) s[threadIdx.x] += t;
        __syncthreads();
    }
    if (i < n) g_ptr[i] = s[threadIdx.x] - v;            // exclusive within block
    if (threadIdx.x == 1023 && blockIdx.x < 256) g_bsum[blockIdx.x] = s[1023];
}

__global__ void k_scan_top(int nb) {
    __shared__ int s[128];
    int v = (threadIdx.x < nb) ? g_bsum[threadIdx.x] : 0;
    s[threadIdx.x] = v;
    __syncthreads();
    for (int off = 1; off < 128; off <<= 1) {
        int t = 0;
        if (threadIdx.x >= off) t = s[threadIdx.x - off];
        __syncthreads();
        if (threadIdx.x >= off) s[threadIdx.x] += t;
        __syncthreads();
    }
    if (threadIdx.x < nb) g_boff[threadIdx.x] = s[threadIdx.x] - v;  // exclusive
}

__global__ void k_scan_add(int n, int e) {
    int i = blockIdx.x * blockDim.x + threadIdx.x;
    if (i < n) {
        int p = g_ptr[i] + g_boff[i >> 10];
        g_ptr[i] = p;
        g_cursor[i] = p;
    }
    if (i == 0) g_ptr[n] = e;
}

__global__ void k_fill(int e) {
    int i = blockIdx.x * blockDim.x + threadIdx.x;
    if (i < e) {
        int2 rc = g_edge[i];
        int pos = atomicAdd(&g_cursor[rc.y], 1);
        g_csr_src[pos] = rc.x;
    }
}

__global__ void k_dis(int n) {
    int i = blockIdx.x * blockDim.x + threadIdx.x;
    if (i < n) g_dis[i] = rsqrtf(1.0f + (float)g_rowdeg[i]);
}

// ---------------- GEMM: g_h = dis[i] * (in @ W^T + b) ------------------------
// in_ext != null : layer 1 (reads x);  null : reads g_act.
__global__ __launch_bounds__(256) void k_gemm(
    const float* __restrict__ in_ext, const float* __restrict__ W,
    const float* __restrict__ bias, int n)
{
    __shared__ float in_s[128 * 36];   // [row][kc] stride 36
    __shared__ float w_s [32 * 128];   // [kc][j]

    const float* in = in_ext ? in_ext : g_act;

    const int tid  = threadIdx.x;
    const int base = blockIdx.x * 128;
    const int tr   = tid >> 4;
    const int tc   = tid & 15;

    float acc[8][8];
#pragma unroll
    for (int i = 0; i < 8; i++)
#pragma unroll
        for (int j = 0; j < 8; j++) acc[i][j] = 0.0f;

    for (int kt = 0; kt < 4; kt++) {
        for (int idx = tid; idx < 128 * 8; idx += 256) {
            int r = idx >> 3, kq = idx & 7;
            float4 v = make_float4(0.f, 0.f, 0.f, 0.f);
            int gr = base + r;
            if (gr < n) v = *(const float4*)(in + (size_t)gr * DD + kt * 32 + kq * 4);
            float* p = in_s + r * 36 + kq * 4;
            p[0] = v.x; p[1] = v.y; p[2] = v.z; p[3] = v.w;
        }
        for (int idx = tid; idx < 128 * 8; idx += 256) {
            int j = idx >> 3, kq = idx & 7;
            float4 v = *(const float4*)(W + (size_t)j * DD + kt * 32 + kq * 4);
            w_s[(kq * 4 + 0) * 128 + j] = v.x;
            w_s[(kq * 4 + 1) * 128 + j] = v.y;
            w_s[(kq * 4 + 2) * 128 + j] = v.z;
            w_s[(kq * 4 + 3) * 128 + j] = v.w;
        }
        __syncthreads();

        const float* a_base = in_s + tr * 8 * 36;
#pragma unroll 8
        for (int k = 0; k < 32; k++) {
            float a[8];
#pragma unroll
            for (int i = 0; i < 8; i++) a[i] = a_base[i * 36 + k];
#pragma unroll
            for (int jj = 0; jj < 8; jj++) {
                float bv = w_s[k * 128 + jj * 16 + tc];
#pragma unroll
                for (int i = 0; i < 8; i++) acc[i][jj] = fmaf(a[i], bv, acc[i][jj]);
            }
        }
        __syncthreads();
    }

#pragma unroll
    for (int i = 0; i < 8; i++) {
        int r = base + tr * 8 + i;
        if (r < n) {
            float dv = g_dis[r];
#pragma unroll
            for (int jj = 0; jj < 8; jj++) {
                int j = jj * 16 + tc;
                g_h[(size_t)r * DD + j] = dv * (acc[i][jj] + bias[j]);
            }
        }
    }
}

// ---------------- CSR aggregate: out[c] = relu(dis[c]*(h[c] + sum_in h[r])) --
// One warp per destination node. No atomics.
__global__ __launch_bounds__(256) void k_agg(float4* __restrict__ out_ext, int n)
{
    int gt   = blockIdx.x * blockDim.x + threadIdx.x;
    int c    = gt >> 5;
    int lane = gt & 31;
    if (c >= n) return;

    const float4* h4 = (const float4*)g_h;
    float4 acc = h4[(size_t)c * 32 + lane];      // self loop
    int beg = g_ptr[c];
    int end = g_ptr[c + 1];

    for (int p = beg; p < end; p += 32) {
        int cnt = end - p; if (cnt > 32) cnt = 32;
        int myidx = (lane < cnt) ? __ldg(&g_csr_src[p + lane]) : 0;
#pragma unroll 4
        for (int j = 0; j < cnt; j++) {
            int r = __shfl_sync(0xffffffffu, myidx, j);
            float4 v = h4[(size_t)r * 32 + lane];
            acc.x += v.x; acc.y += v.y; acc.z += v.z; acc.w += v.w;
        }
    }

    float s = g_dis[c];
    acc.x = fmaxf(acc.x * s, 0.f);
    acc.y = fmaxf(acc.y * s, 0.f);
    acc.z = fmaxf(acc.z * s, 0.f);
    acc.w = fmaxf(acc.w * s, 0.f);

    float4* out = out_ext ? out_ext : (float4*)g_act;
    out[(size_t)c * 32 + lane] = acc;
}

// ---------------- launcher ---------------------------------------------------
extern "C" void kernel_launch(void* const* d_in, const int* in_sizes, int n_in,
                              void* d_out, int out_size)
{
    const float* x = nullptr;
    const int* ei = nullptr;
    const float* Ws[3] = {nullptr, nullptr, nullptr};
    const float* bs[3] = {nullptr, nullptr, nullptr};
    int nx = 0, ne = 0, wi = 0, bi = 0;
    for (int i = 0; i < n_in; i++) {
        int sz = in_sizes[i];
        if (sz == DD * DD)       { if (wi < 3) Ws[wi++] = (const float*)d_in[i]; }
        else if (sz == DD)       { if (bi < 3) bs[bi++] = (const float*)d_in[i]; }
        else if (sz == 2 * EMAX) { ei = (const int*)d_in[i]; ne = sz; }
        else                     { x = (const float*)d_in[i]; nx = sz; }
    }
    if (!x || !ei || wi < 3 || bi < 3) {
        x  = (const float*)d_in[0];  nx = in_sizes[0];
        ei = (const int*)d_in[1];    ne = in_sizes[1];
        Ws[0] = (const float*)d_in[2]; bs[0] = (const float*)d_in[3];
        Ws[1] = (const float*)d_in[4]; bs[1] = (const float*)d_in[5];
        Ws[2] = (const float*)d_in[6]; bs[2] = (const float*)d_in[7];
    }

    int n = nx / DD;  if (n > NMAX) n = NMAX;
    int e = ne / 2;   if (e > EMAX) e = EMAX;

    const int T = 256;
    const int nb_scan = (n + 1023) / 1024;

    k_zero      <<<(n + T - 1) / T, T>>>(n);
    k_count     <<<(e + T - 1) / T, T>>>(ei, e, n);
    k_scan_block<<<nb_scan, 1024>>>(n);
    k_scan_top  <<<1, 128>>>(nb_scan);
    k_scan_add  <<<(n + T - 1) / T, T>>>(n, e);
    k_fill      <<<(e + T - 1) / T, T>>>(e);
    k_dis       <<<(n + T - 1) / T, T>>>(n);

    const int gemm_blocks = (n + 127) / 128;
    const int agg_blocks  = (int)(((long long)n * 32 + T - 1) / T);

    // layer 1
    k_gemm<<<gemm_blocks, 256>>>(x, Ws[0], bs[0], n);
    k_agg <<<agg_blocks, T>>>(nullptr, n);
    // layer 2
    k_gemm<<<gemm_blocks, 256>>>(nullptr, Ws[1], bs[1], n);
    k_agg <<<agg_blocks, T>>>(nullptr, n);
    // layer 3
    k_gemm<<<gemm_blocks, 256>>>(nullptr, Ws[2], bs[2], n);
    k_agg <<<agg_blocks, T>>>((float4*)d_out, n);
}

// round 13
// speedup vs baseline: 3.7491x; 1.2639x over previous
#include <cuda_runtime.h>
#include <cuda_bf16.h>
#include <cstdint>

#define NMAX 100000
#define EMAX 1600000
#define DD   128

// ---------------- scratch ----------------------------------------------------
__device__ float g_h   [(size_t)NMAX * DD];  // gemm output: dis[i]*(W in + b)
__device__ float g_act [(size_t)NMAX * DD];  // agg output (next layer input)
__device__ float g_dis [NMAX];               // (1+outdeg)^-0.5
__device__ int2  g_edge[EMAX];               // (row=src, col=dst)
__device__ int   g_indeg [NMAX];
__device__ int   g_rowdeg[NMAX];
__device__ int   g_ptr   [NMAX + 1];         // CSR by destination
__device__ int   g_cursor[NMAX];
__device__ int   g_csr_src[EMAX];
__device__ int   g_bsum[256];
__device__ int   g_boff[256];

// ---------------- prep -------------------------------------------------------
__global__ void k_zero(int n) {
    int i = blockIdx.x * blockDim.x + threadIdx.x;
    if (i < n) { g_indeg[i] = 0; g_rowdeg[i] = 0; }
}

__global__ void k_count(const int* __restrict__ ei, int e, int n) {
    int i = blockIdx.x * blockDim.x + threadIdx.x;
    if (i < e) {
        int r = ei[i];
        int c = ei[e + i];
        if ((unsigned)r >= (unsigned)n) r = 0;
        if ((unsigned)c >= (unsigned)n) c = 0;
        g_edge[i] = make_int2(r, c);
        atomicAdd(&g_rowdeg[r], 1);
        atomicAdd(&g_indeg[c], 1);
    }
}

__global__ void k_scan_block(int n) {
    __shared__ int s[1024];
    int i = blockIdx.x * 1024 + threadIdx.x;
    int v = (i < n) ? g_indeg[i] : 0;
    s[threadIdx.x] = v;
    __syncthreads();
    for (int off = 1; off < 1024; off <<= 1) {
        int t = 0;
        if (threadIdx.x >= off) t = s[threadIdx.x - off];
        __syncthreads();
        if (threadIdx.x >= off) s[threadIdx.x] += t;
        __syncthreads();
    }
    if (i < n) g_ptr[i] = s[threadIdx.x] - v;
    if (threadIdx.x == 1023 && blockIdx.x < 256) g_bsum[blockIdx.x] = s[1023];
}

__global__ void k_scan_top(int nb) {
    __shared__ int s[128];
    int v = (threadIdx.x < nb) ? g_bsum[threadIdx.x] : 0;
    s[threadIdx.x] = v;
    __syncthreads();
    for (int off = 1; off < 128; off <<= 1) {
        int t = 0;
        if (threadIdx.x >= off) t = s[threadIdx.x - off];
        __syncthreads();
        if (threadIdx.x >= off) s[threadIdx.x] += t;
        __syncthreads();
    }
    if (threadIdx.x < nb) g_boff[threadIdx.x] = s[threadIdx.x] - v;
}

__global__ void k_scan_add(int n, int e) {
    int i = blockIdx.x * blockDim.x + threadIdx.x;
    if (i < n) {
        int p = g_ptr[i] + g_boff[i >> 10];
        g_ptr[i] = p;
        g_cursor[i] = p;
    }
    if (i == 0) g_ptr[n] = e;
}

__global__ void k_fill(int e) {
    int i = blockIdx.x * blockDim.x + threadIdx.x;
    if (i < e) {
        int2 rc = g_edge[i];
        int pos = atomicAdd(&g_cursor[rc.y], 1);
        g_csr_src[pos] = rc.x;
    }
}

__global__ void k_dis(int n) {
    int i = blockIdx.x * blockDim.x + threadIdx.x;
    if (i < n) g_dis[i] = rsqrtf(1.0f + (float)g_rowdeg[i]);
}

// ---------------- TF32 helpers ----------------------------------------------
__device__ __forceinline__ uint32_t f2tf32(float f) {
    uint32_t r;
    asm("cvt.rna.tf32.f32 %0, %1;" : "=r"(r) : "f"(f));
    return r;
}
__device__ __forceinline__ float tf32f(float v) { return __uint_as_float(f2tf32(v)); }

__device__ __forceinline__ void mma_tf32(float c[4], const uint32_t a[4],
                                         const uint32_t b[2]) {
    asm volatile(
        "mma.sync.aligned.m16n8k8.row.col.f32.tf32.tf32.f32 "
        "{%0,%1,%2,%3}, {%4,%5,%6,%7}, {%8,%9}, {%0,%1,%2,%3};"
        : "+f"(c[0]), "+f"(c[1]), "+f"(c[2]), "+f"(c[3])
        : "r"(a[0]), "r"(a[1]), "r"(a[2]), "r"(a[3]), "r"(b[0]), "r"(b[1]));
}

// ---------------- GEMM (3xTF32, direct fragments): g_h = dis*(in @ W^T + b) --
// in_ext != nullptr : layer 1 (reads x).  nullptr : read g_act by symbol.
// Input is read PLAINLY — relu(dis*.) is already applied by k_agg.
// Fragments built straight from the PTX ISA m16n8k8 coordinate formulas.
__global__ __launch_bounds__(256) void k_gemm(
    const float* __restrict__ in_ext, const float* __restrict__ W,
    const float* __restrict__ bias, int n)
{
    __shared__ float w_hi_s[128 * 36];
    __shared__ float w_lo_s[128 * 36];

    const int tid  = threadIdx.x;
    const int wid  = tid >> 5;
    const int lane = tid & 31;
    const int base = blockIdx.x * 128;
    const int g    = lane >> 2;
    const int t    = lane & 3;

    const int r0 = base + wid * 16 + g;
    const int r1 = r0 + 8;
    const bool ok0 = r0 < n, ok1 = r1 < n;
    const float s0 = ok0 ? g_dis[r0] : 0.f;
    const float s1 = ok1 ? g_dis[r1] : 0.f;
    const float* __restrict__ inp = in_ext ? in_ext : g_act;

    float acc[16][4];
#pragma unroll
    for (int nt = 0; nt < 16; nt++)
#pragma unroll
        for (int i = 0; i < 4; i++) acc[nt][i] = 0.0f;

    for (int kc = 0; kc < 4; kc++) {           // 32-wide K chunks
        // stage W[0:128][kc*32 : kc*32+32] as tf32 hi/lo, row-major stride 36
#pragma unroll
        for (int it = 0; it < 4; it++) {
            int idx = tid + it * 256;          // 0..1023
            int j = idx >> 3, q = idx & 7;
            float4 v = *(const float4*)(W + (size_t)j * DD + kc * 32 + q * 4);
            float vv[4] = {v.x, v.y, v.z, v.w};
#pragma unroll
            for (int u = 0; u < 4; u++) {
                float hi = tf32f(vv[u]);
                w_hi_s[j * 36 + q * 4 + u] = hi;
                w_lo_s[j * 36 + q * 4 + u] = tf32f(vv[u] - hi);
            }
        }
        __syncthreads();

#pragma unroll
        for (int ss = 0; ss < 4; ss++) {       // k8 slices within chunk
            int k0 = kc * 32 + ss * 8;
            // A fragment (PTX formulas): a0=(r0,k0+t) a1=(r1,k0+t)
            //                            a2=(r0,k0+t+4) a3=(r1,k0+t+4)
            float av[4];
            av[0] = ok0 ? inp[(size_t)r0 * DD + k0 + t]     : 0.f;
            av[1] = ok1 ? inp[(size_t)r1 * DD + k0 + t]     : 0.f;
            av[2] = ok0 ? inp[(size_t)r0 * DD + k0 + t + 4] : 0.f;
            av[3] = ok1 ? inp[(size_t)r1 * DD + k0 + t + 4] : 0.f;
            uint32_t ahi[4], alo[4];
#pragma unroll
            for (int u = 0; u < 4; u++) {
                float hi = tf32f(av[u]);
                ahi[u] = __float_as_uint(hi);
                alo[u] = f2tf32(av[u] - hi);
            }

#pragma unroll
            for (int nt = 0; nt < 16; nt++) {
                // B fragment: b0 = W[nt*8+g][k0+t], b1 = W[nt*8+g][k0+t+4]
                int jb = (nt * 8 + g) * 36 + ss * 8 + t;
                uint32_t bhi[2], blo[2];
                bhi[0] = __float_as_uint(w_hi_s[jb]);
                bhi[1] = __float_as_uint(w_hi_s[jb + 4]);
                blo[0] = __float_as_uint(w_lo_s[jb]);
                blo[1] = __float_as_uint(w_lo_s[jb + 4]);
                mma_tf32(acc[nt], ahi, bhi);
                mma_tf32(acc[nt], ahi, blo);
                mma_tf32(acc[nt], alo, bhi);
            }
        }
        __syncthreads();
    }

    // epilogue: c0=(r0,2t) c1=(r0,2t+1) c2=(r1,2t) c3=(r1,2t+1), per n-tile
#pragma unroll
    for (int nt = 0; nt < 16; nt++) {
        int j0 = nt * 8 + 2 * t;
        float2 bb = *(const float2*)(bias + j0);
        if (ok0) {
            float2 o;
            o.x = s0 * (acc[nt][0] + bb.x);
            o.y = s0 * (acc[nt][1] + bb.y);
            *(float2*)(g_h + (size_t)r0 * DD + j0) = o;
        }
        if (ok1) {
            float2 o;
            o.x = s1 * (acc[nt][2] + bb.x);
            o.y = s1 * (acc[nt][3] + bb.y);
            *(float2*)(g_h + (size_t)r1 * DD + j0) = o;
        }
    }
}

// ---------------- CSR aggregate: out[c] = relu(dis[c]*(h[c] + sum_in h[r])) --
__global__ __launch_bounds__(256) void k_agg(float4* __restrict__ out_ext, int n)
{
    int gt   = blockIdx.x * blockDim.x + threadIdx.x;
    int c    = gt >> 5;
    int lane = gt & 31;
    if (c >= n) return;

    const float4* h4 = (const float4*)g_h;
    float4 acc = h4[(size_t)c * 32 + lane];      // self loop
    int beg = g_ptr[c];
    int end = g_ptr[c + 1];

    for (int p = beg; p < end; p += 32) {
        int cnt = end - p; if (cnt > 32) cnt = 32;
        int myidx = (lane < cnt) ? __ldg(&g_csr_src[p + lane]) : 0;
#pragma unroll 4
        for (int j = 0; j < cnt; j++) {
            int r = __shfl_sync(0xffffffffu, myidx, j);
            float4 v = h4[(size_t)r * 32 + lane];
            acc.x += v.x; acc.y += v.y; acc.z += v.z; acc.w += v.w;
        }
    }

    float s = g_dis[c];
    acc.x = fmaxf(acc.x * s, 0.f);
    acc.y = fmaxf(acc.y * s, 0.f);
    acc.z = fmaxf(acc.z * s, 0.f);
    acc.w = fmaxf(acc.w * s, 0.f);

    float4* out = out_ext ? out_ext : (float4*)g_act;
    out[(size_t)c * 32 + lane] = acc;
}

// ---------------- launcher ---------------------------------------------------
extern "C" void kernel_launch(void* const* d_in, const int* in_sizes, int n_in,
                              void* d_out, int out_size)
{
    const float* x = nullptr;
    const int* ei = nullptr;
    const float* Ws[3] = {nullptr, nullptr, nullptr};
    const float* bs[3] = {nullptr, nullptr, nullptr};
    int nx = 0, ne = 0, wi = 0, bi = 0;
    for (int i = 0; i < n_in; i++) {
        int sz = in_sizes[i];
        if (sz == DD * DD)       { if (wi < 3) Ws[wi++] = (const float*)d_in[i]; }
        else if (sz == DD)       { if (bi < 3) bs[bi++] = (const float*)d_in[i]; }
        else if (sz == 2 * EMAX) { ei = (const int*)d_in[i]; ne = sz; }
        else                     { x = (const float*)d_in[i]; nx = sz; }
    }
    if (!x || !ei || wi < 3 || bi < 3) {
        x  = (const float*)d_in[0];  nx = in_sizes[0];
        ei = (const int*)d_in[1];    ne = in_sizes[1];
        Ws[0] = (const float*)d_in[2]; bs[0] = (const float*)d_in[3];
        Ws[1] = (const float*)d_in[4]; bs[1] = (const float*)d_in[5];
        Ws[2] = (const float*)d_in[6]; bs[2] = (const float*)d_in[7];
    }

    int n = nx / DD;  if (n > NMAX) n = NMAX;
    int e = ne / 2;   if (e > EMAX) e = EMAX;

    const int T = 256;
    const int nb_scan = (n + 1023) / 1024;

    k_zero      <<<(n + T - 1) / T, T>>>(n);
    k_count     <<<(e + T - 1) / T, T>>>(ei, e, n);
    k_scan_block<<<nb_scan, 1024>>>(n);
    k_scan_top  <<<1, 128>>>(nb_scan);
    k_scan_add  <<<(n + T - 1) / T, T>>>(n, e);
    k_fill      <<<(e + T - 1) / T, T>>>(e);
    k_dis       <<<(n + T - 1) / T, T>>>(n);

    const int gemm_blocks = (n + 127) / 128;
    const int agg_blocks  = (int)(((long long)n * 32 + T - 1) / T);

    // layer 1: gemm reads x;  layers 2/3: nullptr -> kernel reads g_act by symbol
    k_gemm<<<gemm_blocks, 256>>>(x, Ws[0], bs[0], n);
    k_agg <<<agg_blocks, T>>>(nullptr, n);
    k_gemm<<<gemm_blocks, 256>>>(nullptr, Ws[1], bs[1], n);
    k_agg <<<agg_blocks, T>>>(nullptr, n);
    k_gemm<<<gemm_blocks, 256>>>(nullptr, Ws[2], bs[2], n);
    k_agg <<<agg_blocks, T>>>((float4*)d_out, n);
}

// round 14
// speedup vs baseline: 3.8837x; 1.0359x over previous
#include <cuda_runtime.h>
#include <cuda_bf16.h>
#include <cuda_fp16.h>
#include <cstdint>

#define NMAX 100000
#define EMAX 1600000
#define DD   128

// ---------------- scratch ----------------------------------------------------
__device__ __half g_h16[(size_t)NMAX * DD];  // gemm output (fp16): dis[i]*(W in + b)
__device__ float  g_act[(size_t)NMAX * DD];  // agg output fp32 (next layer input)
__device__ float  g_dis[NMAX];               // (1+outdeg)^-0.5
__device__ int2   g_edge[EMAX];              // (row=src, col=dst)
__device__ int    g_indeg [NMAX];
__device__ int    g_rowdeg[NMAX];
__device__ int    g_ptr   [NMAX + 1];        // CSR by destination
__device__ int    g_cursor[NMAX];
__device__ int    g_csr_src[EMAX];
__device__ int    g_bsum[256];
__device__ int    g_boff[256];

// ---------------- prep -------------------------------------------------------
__global__ void k_zero(int n) {
    int i = blockIdx.x * blockDim.x + threadIdx.x;
    if (i < n) { g_indeg[i] = 0; g_rowdeg[i] = 0; }
}

__global__ void k_count(const int* __restrict__ ei, int e, int n) {
    int i = blockIdx.x * blockDim.x + threadIdx.x;
    if (i < e) {
        int r = ei[i];
        int c = ei[e + i];
        if ((unsigned)r >= (unsigned)n) r = 0;
        if ((unsigned)c >= (unsigned)n) c = 0;
        g_edge[i] = make_int2(r, c);
        atomicAdd(&g_rowdeg[r], 1);
        atomicAdd(&g_indeg[c], 1);
    }
}

__global__ void k_scan_block(int n) {
    __shared__ int s[1024];
    int i = blockIdx.x * 1024 + threadIdx.x;
    int v = (i < n) ? g_indeg[i] : 0;
    s[threadIdx.x] = v;
    __syncthreads();
    for (int off = 1; off < 1024; off <<= 1) {
        int t = 0;
        if (threadIdx.x >= off) t = s[threadIdx.x - off];
        __syncthreads();
        if (threadIdx.x >= off) s[threadIdx.x] += t;
        __syncthreads();
    }
    if (i < n) g_ptr[i] = s[threadIdx.x] - v;
    if (threadIdx.x == 1023 && blockIdx.x < 256) g_bsum[blockIdx.x] = s[1023];
}

__global__ void k_scan_top(int nb) {
    __shared__ int s[128];
    int v = (threadIdx.x < nb) ? g_bsum[threadIdx.x] : 0;
    s[threadIdx.x] = v;
    __syncthreads();
    for (int off = 1; off < 128; off <<= 1) {
        int t = 0;
        if (threadIdx.x >= off) t = s[threadIdx.x - off];
        __syncthreads();
        if (threadIdx.x >= off) s[threadIdx.x] += t;
        __syncthreads();
    }
    if (threadIdx.x < nb) g_boff[threadIdx.x] = s[threadIdx.x] - v;
}

// also computes dis (needs only rowdeg)
__global__ void k_scan_add(int n, int e) {
    int i = blockIdx.x * blockDim.x + threadIdx.x;
    if (i < n) {
        int p = g_ptr[i] + g_boff[i >> 10];
        g_ptr[i] = p;
        g_cursor[i] = p;
        g_dis[i] = rsqrtf(1.0f + (float)g_rowdeg[i]);
    }
    if (i == 0) g_ptr[n] = e;
}

__global__ void k_fill(int e) {
    int i = blockIdx.x * blockDim.x + threadIdx.x;
    if (i < e) {
        int2 rc = g_edge[i];
        int pos = atomicAdd(&g_cursor[rc.y], 1);
        g_csr_src[pos] = rc.x;
    }
}

// ---------------- TF32 helpers ----------------------------------------------
__device__ __forceinline__ uint32_t f2tf32(float f) {
    uint32_t r;
    asm("cvt.rna.tf32.f32 %0, %1;" : "=r"(r) : "f"(f));
    return r;
}
__device__ __forceinline__ float tf32f(float v) { return __uint_as_float(f2tf32(v)); }

__device__ __forceinline__ void mma_tf32(float c[4], const uint32_t a[4],
                                         const uint32_t b[2]) {
    asm volatile(
        "mma.sync.aligned.m16n8k8.row.col.f32.tf32.tf32.f32 "
        "{%0,%1,%2,%3}, {%4,%5,%6,%7}, {%8,%9}, {%0,%1,%2,%3};"
        : "+f"(c[0]), "+f"(c[1]), "+f"(c[2]), "+f"(c[3])
        : "r"(a[0]), "r"(a[1]), "r"(a[2]), "r"(a[3]), "r"(b[0]), "r"(b[1]));
}

// ---------------- GEMM (3xTF32, direct fragments): g_h16 = dis*(in@W^T + b) --
// in_ext != nullptr : layer 1 (reads x).  nullptr : read g_act by symbol.
__global__ __launch_bounds__(256) void k_gemm(
    const float* __restrict__ in_ext, const float* __restrict__ W,
    const float* __restrict__ bias, int n)
{
    __shared__ float w_hi_s[128 * 36];
    __shared__ float w_lo_s[128 * 36];

    const int tid  = threadIdx.x;
    const int wid  = tid >> 5;
    const int lane = tid & 31;
    const int base = blockIdx.x * 128;
    const int g    = lane >> 2;
    const int t    = lane & 3;

    const int r0 = base + wid * 16 + g;
    const int r1 = r0 + 8;
    const bool ok0 = r0 < n, ok1 = r1 < n;
    const float s0 = ok0 ? g_dis[r0] : 0.f;
    const float s1 = ok1 ? g_dis[r1] : 0.f;
    const float* __restrict__ inp = in_ext ? in_ext : g_act;

    float acc[16][4];
#pragma unroll
    for (int nt = 0; nt < 16; nt++)
#pragma unroll
        for (int i = 0; i < 4; i++) acc[nt][i] = 0.0f;

    for (int kc = 0; kc < 4; kc++) {           // 32-wide K chunks
#pragma unroll
        for (int it = 0; it < 4; it++) {
            int idx = tid + it * 256;          // 0..1023
            int j = idx >> 3, q = idx & 7;
            float4 v = *(const float4*)(W + (size_t)j * DD + kc * 32 + q * 4);
            float vv[4] = {v.x, v.y, v.z, v.w};
#pragma unroll
            for (int u = 0; u < 4; u++) {
                float hi = tf32f(vv[u]);
                w_hi_s[j * 36 + q * 4 + u] = hi;
                w_lo_s[j * 36 + q * 4 + u] = tf32f(vv[u] - hi);
            }
        }
        __syncthreads();

#pragma unroll
        for (int ss = 0; ss < 4; ss++) {       // k8 slices within chunk
            int k0 = kc * 32 + ss * 8;
            float av[4];
            av[0] = ok0 ? inp[(size_t)r0 * DD + k0 + t]     : 0.f;
            av[1] = ok1 ? inp[(size_t)r1 * DD + k0 + t]     : 0.f;
            av[2] = ok0 ? inp[(size_t)r0 * DD + k0 + t + 4] : 0.f;
            av[3] = ok1 ? inp[(size_t)r1 * DD + k0 + t + 4] : 0.f;
            uint32_t ahi[4], alo[4];
#pragma unroll
            for (int u = 0; u < 4; u++) {
                float hi = tf32f(av[u]);
                ahi[u] = __float_as_uint(hi);
                alo[u] = f2tf32(av[u] - hi);
            }

#pragma unroll
            for (int nt = 0; nt < 16; nt++) {
                int jb = (nt * 8 + g) * 36 + ss * 8 + t;
                uint32_t bhi[2], blo[2];
                bhi[0] = __float_as_uint(w_hi_s[jb]);
                bhi[1] = __float_as_uint(w_hi_s[jb + 4]);
                blo[0] = __float_as_uint(w_lo_s[jb]);
                blo[1] = __float_as_uint(w_lo_s[jb + 4]);
                mma_tf32(acc[nt], ahi, bhi);
                mma_tf32(acc[nt], ahi, blo);
                mma_tf32(acc[nt], alo, bhi);
            }
        }
        __syncthreads();
    }

    // epilogue -> fp16 (half2 per n-tile)
#pragma unroll
    for (int nt = 0; nt < 16; nt++) {
        int j0 = nt * 8 + 2 * t;
        float2 bb = *(const float2*)(bias + j0);
        if (ok0) {
            __half2 o = __floats2half2_rn(s0 * (acc[nt][0] + bb.x),
                                          s0 * (acc[nt][1] + bb.y));
            *(__half2*)(g_h16 + (size_t)r0 * DD + j0) = o;
        }
        if (ok1) {
            __half2 o = __floats2half2_rn(s1 * (acc[nt][2] + bb.x),
                                          s1 * (acc[nt][3] + bb.y));
            *(__half2*)(g_h16 + (size_t)r1 * DD + j0) = o;
        }
    }
}

// ---------------- CSR aggregate (fp16 gather, fp32 accum) --------------------
// out[c] = relu(dis[c]*(h[c] + sum_in h[r])); one warp per destination.
__global__ __launch_bounds__(256) void k_agg(float4* __restrict__ out_ext, int n)
{
    int gt   = blockIdx.x * blockDim.x + threadIdx.x;
    int c    = gt >> 5;
    int lane = gt & 31;
    if (c >= n) return;

    const uint2* h2 = (const uint2*)g_h16;     // 4 halves per uint2; 32 per row
    float4 acc;
    {
        uint2 v = h2[(size_t)c * 32 + lane];   // self loop
        float2 f0 = __half22float2(*(__half2*)&v.x);
        float2 f1 = __half22float2(*(__half2*)&v.y);
        acc.x = f0.x; acc.y = f0.y; acc.z = f1.x; acc.w = f1.y;
    }
    int beg = g_ptr[c];
    int end = g_ptr[c + 1];

    for (int p = beg; p < end; p += 32) {
        int cnt = end - p; if (cnt > 32) cnt = 32;
        int myidx = (lane < cnt) ? __ldg(&g_csr_src[p + lane]) : 0;
#pragma unroll 4
        for (int j = 0; j < cnt; j++) {
            int r = __shfl_sync(0xffffffffu, myidx, j);
            uint2 v = h2[(size_t)r * 32 + lane];
            float2 f0 = __half22float2(*(__half2*)&v.x);
            float2 f1 = __half22float2(*(__half2*)&v.y);
            acc.x += f0.x; acc.y += f0.y; acc.z += f1.x; acc.w += f1.y;
        }
    }

    float s = g_dis[c];
    acc.x = fmaxf(acc.x * s, 0.f);
    acc.y = fmaxf(acc.y * s, 0.f);
    acc.z = fmaxf(acc.z * s, 0.f);
    acc.w = fmaxf(acc.w * s, 0.f);

    float4* out = out_ext ? out_ext : (float4*)g_act;
    out[(size_t)c * 32 + lane] = acc;
}

// ---------------- launcher ---------------------------------------------------
extern "C" void kernel_launch(void* const* d_in, const int* in_sizes, int n_in,
                              void* d_out, int out_size)
{
    const float* x = nullptr;
    const int* ei = nullptr;
    const float* Ws[3] = {nullptr, nullptr, nullptr};
    const float* bs[3] = {nullptr, nullptr, nullptr};
    int nx = 0, ne = 0, wi = 0, bi = 0;
    for (int i = 0; i < n_in; i++) {
        int sz = in_sizes[i];
        if (sz == DD * DD)       { if (wi < 3) Ws[wi++] = (const float*)d_in[i]; }
        else if (sz == DD)       { if (bi < 3) bs[bi++] = (const float*)d_in[i]; }
        else if (sz == 2 * EMAX) { ei = (const int*)d_in[i]; ne = sz; }
        else                     { x = (const float*)d_in[i]; nx = sz; }
    }
    if (!x || !ei || wi < 3 || bi < 3) {
        x  = (const float*)d_in[0];  nx = in_sizes[0];
        ei = (const int*)d_in[1];    ne = in_sizes[1];
        Ws[0] = (const float*)d_in[2]; bs[0] = (const float*)d_in[3];
        Ws[1] = (const float*)d_in[4]; bs[1] = (const float*)d_in[5];
        Ws[2] = (const float*)d_in[6]; bs[2] = (const float*)d_in[7];
    }

    int n = nx / DD;  if (n > NMAX) n = NMAX;
    int e = ne / 2;   if (e > EMAX) e = EMAX;

    const int T = 256;
    const int nb_scan = (n + 1023) / 1024;

    k_zero      <<<(n + T - 1) / T, T>>>(n);
    k_count     <<<(e + T - 1) / T, T>>>(ei, e, n);
    k_scan_block<<<nb_scan, 1024>>>(n);
    k_scan_top  <<<1, 128>>>(nb_scan);
    k_scan_add  <<<(n + T - 1) / T, T>>>(n, e);
    k_fill      <<<(e + T - 1) / T, T>>>(e);

    const int gemm_blocks = (n + 127) / 128;
    const int agg_blocks  = (int)(((long long)n * 32 + T - 1) / T);

    // layer 1: gemm reads x;  layers 2/3: nullptr -> kernel reads g_act by symbol
    k_gemm<<<gemm_blocks, 256>>>(x, Ws[0], bs[0], n);
    k_agg <<<agg_blocks, T>>>(nullptr, n);
    k_gemm<<<gemm_blocks, 256>>>(nullptr, Ws[1], bs[1], n);
    k_agg <<<agg_blocks, T>>>(nullptr, n);
    k_gemm<<<gemm_blocks, 256>>>(nullptr, Ws[2], bs[2], n);
    k_agg <<<agg_blocks, T>>>((float4*)d_out, n);
}